// round 5
// baseline (speedup 1.0000x reference)
#include <cuda_runtime.h>
#include <cuda_bf16.h>
#include <math.h>

#define NN_MAX 50000
#define EE_MAX 600000
#define DD 128
#define HH 4
#define CC 32
#define NEG_SLOPE 0.2f
#define LN_EPS 1e-5f
#define NB_MAX 256

// ---------------- device scratch ----------------
static __device__ float g_h[NN_MAX * DD];
static __device__ float g_asrc[NN_MAX * HH];
static __device__ float g_adst[NN_MAX * HH];
static __device__ int   g_deg[NN_MAX];
static __device__ int   g_rowoff[NN_MAX];
static __device__ int   g_cursor[NN_MAX];
static __device__ int   g_srclist[EE_MAX];
static __device__ int   g_bsum[NB_MAX];
static __device__ int   g_is64;

// ---------------- f32x2 helpers ----------------
__device__ __forceinline__ unsigned long long pk2(float lo, float hi) {
    unsigned long long r;
    asm("mov.b64 %0, {%1, %2};" : "=l"(r) : "f"(lo), "f"(hi));
    return r;
}
__device__ __forceinline__ unsigned long long fma2(unsigned long long a,
                                                   unsigned long long b,
                                                   unsigned long long c) {
    unsigned long long d;
    asm("fma.rn.f32x2 %0, %1, %2, %3;" : "=l"(d) : "l"(a), "l"(b), "l"(c));
    return d;
}
__device__ __forceinline__ float2 upk2(unsigned long long v) {
    float lo, hi;
    asm("mov.b64 {%0, %1}, %2;" : "=f"(lo), "=f"(hi) : "l"(v));
    return make_float2(lo, hi);
}
__device__ __forceinline__ float lrelu(float v) {
    return (v > 0.f) ? v : v * NEG_SLOPE;
}
__device__ __forceinline__ float4 lrelu4(float4 v) {
    return make_float4(lrelu(v.x), lrelu(v.y), lrelu(v.z), lrelu(v.w));
}

// ---------------- Kernel 0: zero degrees + detect dtype ----------------
__global__ void detect_zero_kernel(const int* __restrict__ ei32, int E, int n)
{
    int i = blockIdx.x * 256 + threadIdx.x;
    if (i < n) g_deg[i] = 0;
    if (blockIdx.x == 0) {
        int checks = 2 * E; if (checks > 4096) checks = 4096;
        int nz = 0;
        for (int j = threadIdx.x; j < checks; j += 256)
            if (ei32[2 * j + 1] != 0) nz = 1;
        #pragma unroll
        for (int o = 16; o >= 1; o >>= 1)
            nz |= __shfl_xor_sync(0xffffffffu, nz, o);
        __shared__ int s_nz[8];
        if ((threadIdx.x & 31) == 0) s_nz[threadIdx.x >> 5] = nz;
        __syncthreads();
        if (threadIdx.x == 0) {
            int a = 0;
            for (int w = 0; w < 8; w++) a |= s_nz[w];
            g_is64 = (a == 0) ? 1 : 0;
        }
    }
}

__device__ __forceinline__ int edge_src(const void* ei, int E, int e) {
    if (g_is64) return (int)((const long long*)ei)[e];
    return ((const int*)ei)[e];
}
__device__ __forceinline__ int edge_dst(const void* ei, int E, int e) {
    if (g_is64) return (int)((const long long*)ei)[E + e];
    return ((const int*)ei)[E + e];
}

// ---------------- Kernel 1: h = x @ W + fused attention logits ----------
__global__ __launch_bounds__(256, 2)
void gemm_kernel(const float* __restrict__ x, const float* __restrict__ W,
                 const float* __restrict__ att_src, const float* __restrict__ att_dst,
                 int n)
{
    extern __shared__ float smem[];
    float* ws = smem;              // [128][128]
    float* xs = smem + 128 * 128;  // [64][128]

    int rowbase = blockIdx.x * 64;

    const float4* W4 = (const float4*)W;
    float4* ws4 = (float4*)ws;
    #pragma unroll
    for (int t = threadIdx.x; t < 4096; t += 256) ws4[t] = W4[t];

    float4* xs4 = (float4*)xs;
    const float4* x4in = (const float4*)x;
    #pragma unroll
    for (int t = threadIdx.x; t < 2048; t += 256) {
        int r = t >> 5, k4 = t & 31;
        int grow = rowbase + r;
        float4 v = make_float4(0.f, 0.f, 0.f, 0.f);
        if (grow < n) v = x4in[grow * 32 + k4];
        xs4[r * 32 + k4] = v;
    }
    __syncthreads();

    int rg = threadIdx.x >> 5;
    int cg = threadIdx.x & 31;

    unsigned long long acc0[8], acc1[8];
    #pragma unroll
    for (int i = 0; i < 8; i++) { acc0[i] = 0ull; acc1[i] = 0ull; }

    const float* xrow = xs + rg * 8 * 128;
    const ulonglong2* ws2 = (const ulonglong2*)ws;

    #pragma unroll 4
    for (int k = 0; k < 128; k++) {
        ulonglong2 wv = ws2[k * 32 + cg];
        #pragma unroll
        for (int i = 0; i < 8; i++) {
            float xv = xrow[i * 128 + k];
            unsigned long long xx = pk2(xv, xv);
            acc0[i] = fma2(xx, wv.x, acc0[i]);
            acc1[i] = fma2(xx, wv.y, acc1[i]);
        }
    }

    float4 as4 = ((const float4*)att_src)[cg];
    float4 ad4 = ((const float4*)att_dst)[cg];
    float4* h4 = (float4*)g_h;
    int head = cg >> 3;

    #pragma unroll
    for (int i = 0; i < 8; i++) {
        float2 a = upk2(acc0[i]);
        float2 b = upk2(acc1[i]);
        float4 hv = make_float4(a.x, a.y, b.x, b.y);
        float ps = hv.x * as4.x + hv.y * as4.y + hv.z * as4.z + hv.w * as4.w;
        float pd = hv.x * ad4.x + hv.y * ad4.y + hv.z * ad4.z + hv.w * ad4.w;
        #pragma unroll
        for (int o = 4; o >= 1; o >>= 1) {
            ps += __shfl_xor_sync(0xffffffffu, ps, o);
            pd += __shfl_xor_sync(0xffffffffu, pd, o);
        }
        int grow = rowbase + rg * 8 + i;
        if (grow < n) {
            h4[grow * 32 + cg] = hv;
            if ((cg & 7) == 0) {
                g_asrc[grow * HH + head] = ps;
                g_adst[grow * HH + head] = pd;
            }
        }
    }
}

// ---------------- Kernel 2: histogram of dst ----------------
__global__ void hist_kernel(const void* __restrict__ ei, int E)
{
    int e = blockIdx.x * 256 + threadIdx.x;
    if (e < E) {
        int d = edge_dst(ei, E, e);
        atomicAdd(&g_deg[d], 1);
    }
}

// ---------------- Kernel 3a: per-block local exclusive scan -------------
__global__ __launch_bounds__(256)
void scan_local_kernel(int n)
{
    int i = blockIdx.x * 256 + threadIdx.x;
    int lane = threadIdx.x & 31;
    int wid  = threadIdx.x >> 5;
    int v = (i < n) ? g_deg[i] : 0;

    int inc = v;
    #pragma unroll
    for (int o = 1; o < 32; o <<= 1) {
        int t = __shfl_up_sync(0xffffffffu, inc, o);
        if (lane >= o) inc += t;
    }
    __shared__ int wsum[8];
    if (lane == 31) wsum[wid] = inc;
    __syncthreads();
    if (wid == 0) {
        int ws = (lane < 8) ? wsum[lane] : 0;
        #pragma unroll
        for (int o = 1; o < 8; o <<= 1) {
            int t = __shfl_up_sync(0xffffffffu, ws, o);
            if (lane >= o) ws += t;
        }
        if (lane < 8) wsum[lane] = ws;
    }
    __syncthreads();
    int warpbase = (wid == 0) ? 0 : wsum[wid - 1];
    int excl = warpbase + inc - v;
    if (i < n) g_rowoff[i] = excl;
    if (threadIdx.x == 255) g_bsum[blockIdx.x] = warpbase + inc;
}

// ---------------- Kernel 3b: fixup (each block reduces its own base) ----
__global__ __launch_bounds__(256)
void scan_fixup_kernel(int n, int nb)
{
    // base = sum of g_bsum[j] for j < blockIdx.x  (warp 0 computes, smem bcast)
    __shared__ int s_base;
    if (threadIdx.x < 32) {
        int b = 0;
        for (int j = threadIdx.x; j < blockIdx.x; j += 32) b += g_bsum[j];
        #pragma unroll
        for (int o = 16; o >= 1; o >>= 1)
            b += __shfl_xor_sync(0xffffffffu, b, o);
        if (threadIdx.x == 0) s_base = b;
    }
    __syncthreads();
    int i = blockIdx.x * 256 + threadIdx.x;
    if (i < n) {
        int r = g_rowoff[i] + s_base;
        g_rowoff[i] = r;
        g_cursor[i] = r;
    }
}

// ---------------- Kernel 4: scatter edges into CSR ----------------
__global__ void scatter_kernel(const void* __restrict__ ei, int E)
{
    int e = blockIdx.x * 256 + threadIdx.x;
    if (e < E) {
        int s = edge_src(ei, E, e);
        int d = edge_dst(ei, E, e);
        int pos = atomicAdd(&g_cursor[d], 1);
        g_srclist[pos] = s;
    }
}

// ---------------- Kernel 5: fused softmax-agg + GELU + LN + residual ----
// One warp per node. Lane-parallel edge preprocessing: lane k handles edge k
// (all 4 heads at once as float4), staged to smem; then the aggregation loop
// does ONLY the h gather + FMA per edge.
__global__ __launch_bounds__(256)
void agg_ln_kernel(const float* __restrict__ x,
                   const float* __restrict__ bias,
                   const float* __restrict__ gamma,
                   const float* __restrict__ beta,
                   float* __restrict__ out, int n)
{
    __shared__ float sp[8][32 * 4];   // per-warp per-edge p for 4 heads
    __shared__ int   ssid[8][32];

    int w = threadIdx.x >> 5;
    int node = blockIdx.x * 8 + w;
    if (node >= n) return;
    int lane = threadIdx.x & 31;
    int hd8 = lane >> 3;              // head owning this lane's channels

    int beg = g_rowoff[node];
    int cnt = g_deg[node];

    float4 adst4  = ((const float4*)g_adst)[node];
    float4 aself4 = ((const float4*)g_asrc)[node];
    const float4* asrc4p = (const float4*)g_asrc;

    // ---- Pass 1: per-head max of a_src over {self} U neighbors ----
    float4 m4 = aself4;
    int   sid0 = 0;                   // chunk-0 cache (common case cnt<=32)
    float4 a40 = make_float4(0.f, 0.f, 0.f, 0.f);
    for (int base = 0; base < cnt; base += 32) {
        int k = base + lane;
        int sid = (k < cnt) ? g_srclist[beg + k] : 0;
        float4 a4 = (k < cnt) ? asrc4p[sid]
                              : make_float4(-1e30f, -1e30f, -1e30f, -1e30f);
        if (base == 0) { sid0 = sid; a40 = a4; }
        m4.x = fmaxf(m4.x, a4.x); m4.y = fmaxf(m4.y, a4.y);
        m4.z = fmaxf(m4.z, a4.z); m4.w = fmaxf(m4.w, a4.w);
    }
    #pragma unroll
    for (int o = 16; o >= 1; o >>= 1) {
        m4.x = fmaxf(m4.x, __shfl_xor_sync(0xffffffffu, m4.x, o));
        m4.y = fmaxf(m4.y, __shfl_xor_sync(0xffffffffu, m4.y, o));
        m4.z = fmaxf(m4.z, __shfl_xor_sync(0xffffffffu, m4.z, o));
        m4.w = fmaxf(m4.w, __shfl_xor_sync(0xffffffffu, m4.w, o));
    }
    float4 M4 = lrelu4(make_float4(m4.x + adst4.x, m4.y + adst4.y,
                                   m4.z + adst4.z, m4.w + adst4.w));

    // self-loop contribution
    float4 es4 = lrelu4(make_float4(aself4.x + adst4.x, aself4.y + adst4.y,
                                    aself4.z + adst4.z, aself4.w + adst4.w));
    float4 ps4 = make_float4(__expf(es4.x - M4.x), __expf(es4.y - M4.y),
                             __expf(es4.z - M4.z), __expf(es4.w - M4.w));
    float pself = (hd8 == 0) ? ps4.x : (hd8 == 1) ? ps4.y : (hd8 == 2) ? ps4.z : ps4.w;

    const float4* h4 = (const float4*)g_h;
    float4 hv0 = h4[node * 32 + lane];
    float4 acc = make_float4(pself * hv0.x, pself * hv0.y,
                             pself * hv0.z, pself * hv0.w);
    float4 den4 = ps4;   // lane-local partial (identical across lanes for self term;
                         // divide by 32 at reduce? No — keep self only once: zero it on lanes != 0
    if (lane != 0) den4 = make_float4(0.f, 0.f, 0.f, 0.f);

    // ---- Pass 2 per chunk: compute p, stage to smem, aggregate ----
    for (int base = 0; base < cnt; base += 32) {
        int k = base + lane;
        int sid; float4 a4;
        if (base == 0) { sid = sid0; a4 = a40; }
        else {
            sid = (k < cnt) ? g_srclist[beg + k] : 0;
            a4 = (k < cnt) ? asrc4p[sid]
                           : make_float4(-1e30f, -1e30f, -1e30f, -1e30f);
        }
        float4 e4 = lrelu4(make_float4(a4.x + adst4.x, a4.y + adst4.y,
                                       a4.z + adst4.z, a4.w + adst4.w));
        float4 p4 = make_float4(0.f, 0.f, 0.f, 0.f);
        if (k < cnt) {
            p4 = make_float4(__expf(e4.x - M4.x), __expf(e4.y - M4.y),
                             __expf(e4.z - M4.z), __expf(e4.w - M4.w));
        }
        den4.x += p4.x; den4.y += p4.y; den4.z += p4.z; den4.w += p4.w;

        ((float4*)sp[w])[lane] = p4;
        ssid[w][lane] = sid;
        __syncwarp();

        int cc = cnt - base; if (cc > 32) cc = 32;
        int j = 0;
        for (; j + 4 <= cc; j += 4) {
            int s0 = ssid[w][j],     s1 = ssid[w][j + 1];
            int s2 = ssid[w][j + 2], s3 = ssid[w][j + 3];
            float q0 = sp[w][(j    ) * 4 + hd8];
            float q1 = sp[w][(j + 1) * 4 + hd8];
            float q2 = sp[w][(j + 2) * 4 + hd8];
            float q3 = sp[w][(j + 3) * 4 + hd8];
            float4 h0 = h4[s0 * 32 + lane];
            float4 h1 = h4[s1 * 32 + lane];
            float4 h2 = h4[s2 * 32 + lane];
            float4 h3 = h4[s3 * 32 + lane];
            acc.x = fmaf(q0, h0.x, acc.x); acc.y = fmaf(q0, h0.y, acc.y);
            acc.z = fmaf(q0, h0.z, acc.z); acc.w = fmaf(q0, h0.w, acc.w);
            acc.x = fmaf(q1, h1.x, acc.x); acc.y = fmaf(q1, h1.y, acc.y);
            acc.z = fmaf(q1, h1.z, acc.z); acc.w = fmaf(q1, h1.w, acc.w);
            acc.x = fmaf(q2, h2.x, acc.x); acc.y = fmaf(q2, h2.y, acc.y);
            acc.z = fmaf(q2, h2.z, acc.z); acc.w = fmaf(q2, h2.w, acc.w);
            acc.x = fmaf(q3, h3.x, acc.x); acc.y = fmaf(q3, h3.y, acc.y);
            acc.z = fmaf(q3, h3.z, acc.z); acc.w = fmaf(q3, h3.w, acc.w);
        }
        for (; j < cc; j++) {
            int s0 = ssid[w][j];
            float q0 = sp[w][j * 4 + hd8];
            float4 h0 = h4[s0 * 32 + lane];
            acc.x = fmaf(q0, h0.x, acc.x); acc.y = fmaf(q0, h0.y, acc.y);
            acc.z = fmaf(q0, h0.z, acc.z); acc.w = fmaf(q0, h0.w, acc.w);
        }
        __syncwarp();
    }

    // reduce denominator across lanes (per head)
    #pragma unroll
    for (int o = 16; o >= 1; o >>= 1) {
        den4.x += __shfl_xor_sync(0xffffffffu, den4.x, o);
        den4.y += __shfl_xor_sync(0xffffffffu, den4.y, o);
        den4.z += __shfl_xor_sync(0xffffffffu, den4.z, o);
        den4.w += __shfl_xor_sync(0xffffffffu, den4.w, o);
    }
    float den = (hd8 == 0) ? den4.x : (hd8 == 1) ? den4.y : (hd8 == 2) ? den4.z : den4.w;
    float inv = 1.0f / den;

    float4 bi = ((const float4*)bias)[lane];
    float4 o = make_float4(fmaf(acc.x, inv, bi.x), fmaf(acc.y, inv, bi.y),
                           fmaf(acc.z, inv, bi.z), fmaf(acc.w, inv, bi.w));

    const float RS2 = 0.70710678118654752f;
    float4 f;
    f.x = 0.5f * o.x * (1.0f + erff(o.x * RS2));
    f.y = 0.5f * o.y * (1.0f + erff(o.y * RS2));
    f.z = 0.5f * o.z * (1.0f + erff(o.z * RS2));
    f.w = 0.5f * o.w * (1.0f + erff(o.w * RS2));

    float s1 = f.x + f.y + f.z + f.w;
    float s2 = f.x * f.x + f.y * f.y + f.z * f.z + f.w * f.w;
    #pragma unroll
    for (int off = 16; off >= 1; off >>= 1) {
        s1 += __shfl_xor_sync(0xffffffffu, s1, off);
        s2 += __shfl_xor_sync(0xffffffffu, s2, off);
    }
    float mu  = s1 * (1.0f / 128.0f);
    float var = s2 * (1.0f / 128.0f) - mu * mu;
    float r = rsqrtf(var + LN_EPS);

    float4 gm = ((const float4*)gamma)[lane];
    float4 bt = ((const float4*)beta)[lane];
    float4 xv = ((const float4*)x)[node * 32 + lane];
    float4 res;
    res.x = (f.x - mu) * r * gm.x + bt.x + xv.x;
    res.y = (f.y - mu) * r * gm.y + bt.y + xv.y;
    res.z = (f.z - mu) * r * gm.z + bt.z + xv.z;
    res.w = (f.w - mu) * r * gm.w + bt.w + xv.w;
    ((float4*)out)[node * 32 + lane] = res;
}

// ---------------- launch ----------------
extern "C" void kernel_launch(void* const* d_in, const int* in_sizes, int n_in,
                              void* d_out, int out_size)
{
    const float* x       = (const float*)d_in[0];
    const void*  ei      = d_in[1];
    const float* W       = (const float*)d_in[2];
    const float* att_src = (const float*)d_in[3];
    const float* att_dst = (const float*)d_in[4];
    const float* bias    = (const float*)d_in[5];
    const float* gamma   = (const float*)d_in[6];
    const float* beta    = (const float*)d_in[7];
    float*       out     = (float*)d_out;

    int n = in_sizes[0] / DD;     // 50000
    int E = in_sizes[1] / 2;      // 600000
    int nb = (n + 255) / 256;     // 196

    const int GEMM_SMEM = (128 * 128 + 64 * 128) * 4;  // 96KB
    cudaFuncSetAttribute(gemm_kernel, cudaFuncAttributeMaxDynamicSharedMemorySize, GEMM_SMEM);

    detect_zero_kernel<<<nb, 256>>>((const int*)ei, E, n);
    gemm_kernel<<<(n + 63) / 64, 256, GEMM_SMEM>>>(x, W, att_src, att_dst, n);
    hist_kernel<<<(E + 255) / 256, 256>>>(ei, E);
    scan_local_kernel<<<nb, 256>>>(n);
    scan_fixup_kernel<<<nb, 256>>>(n, nb);
    scatter_kernel<<<(E + 255) / 256, 256>>>(ei, E);
    agg_ln_kernel<<<(n + 7) / 8, 256>>>(x, bias, gamma, beta, out, n);
}